// round 15
// baseline (speedup 1.0000x reference)
#include <cuda_runtime.h>
#include <cuda_bf16.h>
#include <math.h>
#include <stdint.h>

// Problem constants
#define BATCH 4096
#define DIM   512
#define NTOT  8192
#define TILE  128
#define KCHUNK 64
#define NCHUNKS (DIM / KCHUNK)   // 8
#define NTILES  (NTOT / TILE)    // 64
#define NCTAS   (NTILES * (NTILES + 1) / 2)  // 2080 upper-tri tiles

// SMEM: double-buffered A and B tiles, each 128 rows x 64 bf16 = 16 KB
#define TILE_BYTES 16384
#define SM_A(buf) ((buf) * TILE_BYTES)
#define SM_B(buf) (2 * TILE_BYTES + (buf) * TILE_BYTES)
#define SM_TOTAL  (4 * TILE_BYTES)   // 64 KB -> 2 CTAs/SM

// Scratch (no cudaMalloc allowed)
__device__ __nv_bfloat16 g_zb[NTOT * DIM];   // normalized Z, bf16 (8 MB)
__device__ float g_denom[NTOT];
__device__ float g_pos[NTOT];

// ---------------------------------------------------------------------------
__device__ __forceinline__ uint32_t smem_u32(const void* p) {
    uint32_t a;
    asm("{ .reg .u64 t; cvta.to.shared.u64 t, %1; cvt.u32.u64 %0, t; }" : "=r"(a) : "l"(p));
    return a;
}

__device__ __forceinline__ void cp_async16(uint32_t saddr, const void* gptr) {
    asm volatile("cp.async.cg.shared.global [%0], [%1], 16;" :: "r"(saddr), "l"(gptr));
}
__device__ __forceinline__ void cp_commit() {
    asm volatile("cp.async.commit_group;" ::: "memory");
}
template <int N>
__device__ __forceinline__ void cp_wait() {
    asm volatile("cp.async.wait_group %0;" :: "n"(N) : "memory");
}

__device__ __forceinline__ void ldsm_x4(uint32_t* r, uint32_t addr) {
    asm volatile("ldmatrix.sync.aligned.m8n8.x4.shared.b16 {%0,%1,%2,%3}, [%4];"
                 : "=r"(r[0]), "=r"(r[1]), "=r"(r[2]), "=r"(r[3]) : "r"(addr));
}

__device__ __forceinline__ void mma16816(float* c, const uint32_t* a, const uint32_t* b) {
    asm volatile(
        "mma.sync.aligned.m16n8k16.row.col.f32.bf16.bf16.f32 "
        "{%0,%1,%2,%3}, {%4,%5,%6,%7}, {%8,%9}, {%0,%1,%2,%3};"
        : "+f"(c[0]), "+f"(c[1]), "+f"(c[2]), "+f"(c[3])
        : "r"(a[0]), "r"(a[1]), "r"(a[2]), "r"(a[3]), "r"(b[0]), "r"(b[1]));
}

// Fast exp(2*s) on the FMA pipe (avoid MUFU.EX2 throughput wall).
__device__ __forceinline__ float fast_exp2s(float s) {
    float t = 2.8853900817779268f * s;      // 2 * log2(e)
    float fn = rintf(t);
    float f = t - fn;
    float p = fmaf(0.0013333558f, f, 0.0096181291f);
    p = fmaf(p, f, 0.0555041087f);
    p = fmaf(p, f, 0.2402265070f);
    p = fmaf(p, f, 0.6931471806f);
    p = fmaf(p, f, 1.0f);
    int n = (int)fn;
    float scale = __int_as_float((n + 127) << 23);
    return p * scale;
}

// ---------------------------------------------------------------------------
// Kernel 1: L2-normalize rows into bf16 Z. ONE warp per row (R9 shape:
// 1024 blocks x 256 threads, occ ~76%, measured 7.2 us). Zeroes accumulators
// and the output scalar.
// ---------------------------------------------------------------------------
__global__ __launch_bounds__(256) void norm_kernel(const float* __restrict__ xi,
                                                   const float* __restrict__ xj,
                                                   float* __restrict__ out) {
    const int row = (blockIdx.x * 256 + threadIdx.x) >> 5;
    const int lane = threadIdx.x & 31;
    const float* src = (row < BATCH) ? (xi + (size_t)row * DIM)
                                     : (xj + (size_t)(row - BATCH) * DIM);
    float4 v[4];
    #pragma unroll
    for (int i = 0; i < 4; i++) v[i] = ((const float4*)src)[lane + 32 * i];

    float ss = 0.0f;
    #pragma unroll
    for (int i = 0; i < 4; i++)
        ss += v[i].x * v[i].x + v[i].y * v[i].y + v[i].z * v[i].z + v[i].w * v[i].w;
    #pragma unroll
    for (int o = 16; o > 0; o >>= 1) ss += __shfl_xor_sync(0xFFFFFFFFu, ss, o);

    const float inv = 1.0f / fmaxf(sqrtf(ss), 1e-12f);

    #pragma unroll
    for (int i = 0; i < 4; i++) {
        __nv_bfloat162 h0 = __floats2bfloat162_rn(v[i].x * inv, v[i].y * inv);
        __nv_bfloat162 h1 = __floats2bfloat162_rn(v[i].z * inv, v[i].w * inv);
        uint2 u;
        u.x = *(uint32_t*)&h0;
        u.y = *(uint32_t*)&h1;
        ((uint2*)(g_zb + (size_t)row * DIM))[lane + 32 * i] = u;
    }

    if (lane == 0) {
        g_denom[row] = 0.0f;
        g_pos[row] = 0.0f;
    }
    if (blockIdx.x == 0 && threadIdx.x == 0) out[0] = 0.0f;
}

// ---------------------------------------------------------------------------
// Kernel 2: symmetric-aware fused sim tiles (upper-tri only) — EXACT R9/R12
// body, full grid 2080. Best measured configuration. DO NOT TOUCH.
// ---------------------------------------------------------------------------
__global__ __launch_bounds__(256, 2) void sim_kernel() {
    extern __shared__ char smem[];
    const uint32_t sbase = smem_u32(smem);
    const int tid = threadIdx.x;
    const int wid = tid >> 5;
    const int lane = tid & 31;

    // triangular decode: off(i) = i*64 - i*(i-1)/2
    const int t = blockIdx.x;
    int by = (int)(64.5f - sqrtf(64.5f * 64.5f - 2.0f * (float)t));
    while ((by + 1) * NTILES - ((by + 1) * by) / 2 <= t) by++;
    while (by * NTILES - (by * (by - 1)) / 2 > t) by--;
    const int bx = by + (t - (by * NTILES - (by * (by - 1)) / 2));

    const int rowBase = by * TILE;
    const int colBase = bx * TILE;
    const bool diag = (by == bx);

    const int warp_m = wid & 3;     // 0..3 -> 32-row strip
    const int warp_n = wid >> 2;    // 0..1 -> 64-col strip

    const __nv_bfloat16* __restrict__ zb = g_zb;

    // --- cp.async load mapping: 1024 16B units per tile, 4 per thread ---
    uint32_t ld_soff[4];
    const __nv_bfloat16* ld_ga[4];
    const __nv_bfloat16* ld_gb[4];
    #pragma unroll
    for (int it = 0; it < 4; it++) {
        int idx = tid + it * 256;
        int r = idx >> 3;
        int c16 = idx & 7;
        ld_soff[it] = (uint32_t)(r * 128 + ((c16 * 16) ^ ((r & 7) << 4)));
        ld_ga[it] = zb + (size_t)(rowBase + r) * DIM + c16 * 8;
        ld_gb[it] = zb + (size_t)(colBase + r) * DIM + c16 * 8;
    }

    // --- ldmatrix address components (swizzle folded into col xor) ---
    uint32_t aRow[2], aMask[2];
    #pragma unroll
    for (int mt = 0; mt < 2; mt++) {
        int r = warp_m * 32 + mt * 16 + (lane & 15);
        aRow[mt] = (uint32_t)(r * 128);
        aMask[mt] = (uint32_t)((r & 7) << 4);
    }
    const uint32_t aColK = (uint32_t)((lane >> 4) * 16);

    uint32_t bRow[4], bMask[4];
    const int q = lane >> 3;
    #pragma unroll
    for (int p = 0; p < 4; p++) {
        int r = warp_n * 64 + (2 * p + (q >> 1)) * 8 + (lane & 7);
        bRow[p] = (uint32_t)(r * 128);
        bMask[p] = (uint32_t)((r & 7) << 4);
    }
    const uint32_t bColK = (uint32_t)((q & 1) * 16);

    float acc[2][8][4];
    #pragma unroll
    for (int mt = 0; mt < 2; mt++)
        #pragma unroll
        for (int nt = 0; nt < 8; nt++)
            #pragma unroll
            for (int k = 0; k < 4; k++) acc[mt][nt][k] = 0.0f;

    // --- prologue: chunk 0 -> buffer 0 ---
    #pragma unroll
    for (int it = 0; it < 4; it++) {
        cp_async16(sbase + SM_A(0) + ld_soff[it], ld_ga[it]);
        cp_async16(sbase + SM_B(0) + ld_soff[it], ld_gb[it]);
    }
    cp_commit();

    for (int kk = 0; kk < NCHUNKS; kk++) {
        const int buf = kk & 1;
        if (kk + 1 < NCHUNKS) {
            const int nb = (kk + 1) & 1;
            const int koff = (kk + 1) * KCHUNK;
            #pragma unroll
            for (int it = 0; it < 4; it++) {
                cp_async16(sbase + SM_A(nb) + ld_soff[it], ld_ga[it] + koff);
                cp_async16(sbase + SM_B(nb) + ld_soff[it], ld_gb[it] + koff);
            }
            cp_commit();
            cp_wait<1>();
        } else {
            cp_wait<0>();
        }
        __syncthreads();

        const uint32_t abase = sbase + SM_A(buf);
        const uint32_t bbase = sbase + SM_B(buf);

        #pragma unroll
        for (int kt = 0; kt < 4; kt++) {
            const uint32_t kb = (uint32_t)(kt * 32);
            uint32_t a[2][4];
            #pragma unroll
            for (int mt = 0; mt < 2; mt++)
                ldsm_x4(a[mt], abase + aRow[mt] + ((kb + aColK) ^ aMask[mt]));

            uint32_t b[8][2];
            #pragma unroll
            for (int p = 0; p < 4; p++) {
                uint32_t r4[4];
                ldsm_x4(r4, bbase + bRow[p] + ((kb + bColK) ^ bMask[p]));
                b[2 * p][0] = r4[0]; b[2 * p][1] = r4[1];
                b[2 * p + 1][0] = r4[2]; b[2 * p + 1][1] = r4[3];
            }

            #pragma unroll
            for (int mt = 0; mt < 2; mt++)
                #pragma unroll
                for (int nt = 0; nt < 8; nt++)
                    mma16816(acc[mt][nt], a[mt], b[nt]);
        }
        __syncthreads();   // protect buffers before next iteration's cp.async
    }

    // --- fused epilogue ---
    const int g = lane >> 2;
    const int cb0 = colBase + warp_n * 64 + (lane & 3) * 2;

    if (diag) {
        #pragma unroll
        for (int mt = 0; mt < 2; mt++) {
            const int r_lo = rowBase + warp_m * 32 + mt * 16 + g;
            const int r_hi = r_lo + 8;
            float sum_lo = 0.0f, sum_hi = 0.0f;
            #pragma unroll
            for (int nt = 0; nt < 8; nt++) {
                const int c0 = cb0 + nt * 8;
                if (c0 != r_lo)     sum_lo += fast_exp2s(acc[mt][nt][0]);
                if (c0 + 1 != r_lo) sum_lo += fast_exp2s(acc[mt][nt][1]);
                if (c0 != r_hi)     sum_hi += fast_exp2s(acc[mt][nt][2]);
                if (c0 + 1 != r_hi) sum_hi += fast_exp2s(acc[mt][nt][3]);
            }
            #pragma unroll
            for (int o = 1; o < 4; o <<= 1) {
                sum_lo += __shfl_xor_sync(0xFFFFFFFFu, sum_lo, o);
                sum_hi += __shfl_xor_sync(0xFFFFFFFFu, sum_hi, o);
            }
            if ((lane & 3) == 0) {
                atomicAdd(&g_denom[r_lo], sum_lo);
                atomicAdd(&g_denom[r_hi], sum_hi);
            }
        }
    } else {
        // off-diagonal: every exp feeds a row sum AND a column sum (symmetry).
        float csum[8][2];
        #pragma unroll
        for (int nt = 0; nt < 8; nt++) { csum[nt][0] = 0.0f; csum[nt][1] = 0.0f; }

        #pragma unroll
        for (int mt = 0; mt < 2; mt++) {
            const int r_lo = rowBase + warp_m * 32 + mt * 16 + g;
            const int r_hi = r_lo + 8;
            const int p_lo = r_lo + BATCH;   // rows < cols here
            const int p_hi = r_hi + BATCH;

            float sum_lo = 0.0f, sum_hi = 0.0f;
            #pragma unroll
            for (int nt = 0; nt < 8; nt++) {
                const int c0 = cb0 + nt * 8;
                const float s00 = acc[mt][nt][0];
                const float s01 = acc[mt][nt][1];
                const float s10 = acc[mt][nt][2];
                const float s11 = acc[mt][nt][3];
                const float e00 = fast_exp2s(s00);
                const float e01 = fast_exp2s(s01);
                const float e10 = fast_exp2s(s10);
                const float e11 = fast_exp2s(s11);
                sum_lo += e00 + e01;
                sum_hi += e10 + e11;
                csum[nt][0] += e00 + e10;
                csum[nt][1] += e01 + e11;
                if (c0 == p_lo)     { g_pos[r_lo] = s00; g_pos[c0] = s00; }
                if (c0 + 1 == p_lo) { g_pos[r_lo] = s01; g_pos[c0 + 1] = s01; }
                if (c0 == p_hi)     { g_pos[r_hi] = s10; g_pos[c0] = s10; }
                if (c0 + 1 == p_hi) { g_pos[r_hi] = s11; g_pos[c0 + 1] = s11; }
            }
            #pragma unroll
            for (int o = 1; o < 4; o <<= 1) {
                sum_lo += __shfl_xor_sync(0xFFFFFFFFu, sum_lo, o);
                sum_hi += __shfl_xor_sync(0xFFFFFFFFu, sum_hi, o);
            }
            if ((lane & 3) == 0) {
                atomicAdd(&g_denom[r_lo], sum_lo);
                atomicAdd(&g_denom[r_hi], sum_hi);
            }
        }

        #pragma unroll
        for (int nt = 0; nt < 8; nt++) {
            float c0s = csum[nt][0];
            float c1s = csum[nt][1];
            #pragma unroll
            for (int o = 4; o < 32; o <<= 1) {
                c0s += __shfl_xor_sync(0xFFFFFFFFu, c0s, o);
                c1s += __shfl_xor_sync(0xFFFFFFFFu, c1s, o);
            }
            if (g == 0) {
                const int c0 = cb0 + nt * 8;
                atomicAdd(&g_denom[c0], c0s);
                atomicAdd(&g_denom[c0 + 1], c1s);
            }
        }
    }
}

// ---------------------------------------------------------------------------
// Kernel 3: distributed final reduction — 32 blocks x 256 threads, __logf
// (MUFU.LG2), shfl-based block reduce, one atomicAdd per block into out
// (zeroed by norm_kernel).
// ---------------------------------------------------------------------------
__global__ __launch_bounds__(256) void reduce_kernel(float* __restrict__ out) {
    const int i = blockIdx.x * 256 + threadIdx.x;
    float v = __logf(g_denom[i]) - 2.0f * g_pos[i];
    #pragma unroll
    for (int o = 16; o > 0; o >>= 1) v += __shfl_xor_sync(0xFFFFFFFFu, v, o);

    __shared__ float ws[8];
    if ((threadIdx.x & 31) == 0) ws[threadIdx.x >> 5] = v;
    __syncthreads();
    if (threadIdx.x < 32) {
        float s = (threadIdx.x < 8) ? ws[threadIdx.x] : 0.0f;
        #pragma unroll
        for (int o = 4; o > 0; o >>= 1) s += __shfl_xor_sync(0xFFFFFFFFu, s, o);
        if (threadIdx.x == 0) atomicAdd(out, s * (1.0f / (float)NTOT));
    }
}

// ---------------------------------------------------------------------------
extern "C" void kernel_launch(void* const* d_in, const int* in_sizes, int n_in,
                              void* d_out, int out_size) {
    const float* x_i = (const float*)d_in[0];
    const float* x_j = (const float*)d_in[1];
    float* out = (float*)d_out;

    cudaFuncSetAttribute(sim_kernel, cudaFuncAttributeMaxDynamicSharedMemorySize, SM_TOTAL);

    norm_kernel<<<NTOT / 8, 256>>>(x_i, x_j, out);    // 1024 blocks, 1 row/warp
    sim_kernel<<<NCTAS, 256, SM_TOTAL>>>();           // full 2080-tile grid
    reduce_kernel<<<NTOT / 256, 256>>>(out);          // 32 blocks
}

// round 17
// speedup vs baseline: 1.5269x; 1.5269x over previous
#include <cuda_runtime.h>
#include <cuda_bf16.h>
#include <math.h>
#include <stdint.h>

// Problem constants
#define BATCH 4096
#define DIM   512
#define NTOT  8192
#define TILE  128
#define KCHUNK 64
#define NCHUNKS (DIM / KCHUNK)   // 8
#define NTILES  (NTOT / TILE)    // 64
#define NCTAS   (NTILES * (NTILES + 1) / 2)  // 2080 upper-tri tiles

// SMEM: double-buffered A and B tiles, each 128 rows x 64 bf16 = 16 KB
#define TILE_BYTES 16384
#define SM_A(buf) ((buf) * TILE_BYTES)
#define SM_B(buf) (2 * TILE_BYTES + (buf) * TILE_BYTES)
#define SM_TOTAL  (4 * TILE_BYTES)   // 64 KB -> 2 CTAs/SM

// Scratch (no cudaMalloc allowed)
__device__ __nv_bfloat16 g_zb[NTOT * DIM];   // normalized Z, bf16 (8 MB)
__device__ float g_denom[NTOT];
__device__ float g_pos[NTOT];

// ---------------------------------------------------------------------------
__device__ __forceinline__ uint32_t smem_u32(const void* p) {
    uint32_t a;
    asm("{ .reg .u64 t; cvta.to.shared.u64 t, %1; cvt.u32.u64 %0, t; }" : "=r"(a) : "l"(p));
    return a;
}

__device__ __forceinline__ void cp_async16(uint32_t saddr, const void* gptr) {
    asm volatile("cp.async.cg.shared.global [%0], [%1], 16;" :: "r"(saddr), "l"(gptr));
}
__device__ __forceinline__ void cp_commit() {
    asm volatile("cp.async.commit_group;" ::: "memory");
}
template <int N>
__device__ __forceinline__ void cp_wait() {
    asm volatile("cp.async.wait_group %0;" :: "n"(N) : "memory");
}

__device__ __forceinline__ void ldsm_x4(uint32_t* r, uint32_t addr) {
    asm volatile("ldmatrix.sync.aligned.m8n8.x4.shared.b16 {%0,%1,%2,%3}, [%4];"
                 : "=r"(r[0]), "=r"(r[1]), "=r"(r[2]), "=r"(r[3]) : "r"(addr));
}

__device__ __forceinline__ void mma16816(float* c, const uint32_t* a, const uint32_t* b) {
    asm volatile(
        "mma.sync.aligned.m16n8k16.row.col.f32.bf16.bf16.f32 "
        "{%0,%1,%2,%3}, {%4,%5,%6,%7}, {%8,%9}, {%0,%1,%2,%3};"
        : "+f"(c[0]), "+f"(c[1]), "+f"(c[2]), "+f"(c[3])
        : "r"(a[0]), "r"(a[1]), "r"(a[2]), "r"(a[3]), "r"(b[0]), "r"(b[1]));
}

// Fast exp(2*s) on the FMA pipe (avoid MUFU.EX2 throughput wall).
__device__ __forceinline__ float fast_exp2s(float s) {
    float t = 2.8853900817779268f * s;      // 2 * log2(e)
    float fn = rintf(t);
    float f = t - fn;
    float p = fmaf(0.0013333558f, f, 0.0096181291f);
    p = fmaf(p, f, 0.0555041087f);
    p = fmaf(p, f, 0.2402265070f);
    p = fmaf(p, f, 0.6931471806f);
    p = fmaf(p, f, 1.0f);
    int n = (int)fn;
    float scale = __int_as_float((n + 127) << 23);
    return p * scale;
}

// ---------------------------------------------------------------------------
// Kernel 1: L2-normalize rows into bf16 Z. One warp handles TWO rows, loads
// front-batched. Zeroes accumulators and the output scalar. (Exact R12/R14.)
// ---------------------------------------------------------------------------
__global__ __launch_bounds__(256) void norm_kernel(const float* __restrict__ xi,
                                                   const float* __restrict__ xj,
                                                   float* __restrict__ out) {
    const int warp = (blockIdx.x * 256 + threadIdx.x) >> 5;   // 0..4095
    const int lane = threadIdx.x & 31;
    const int row0 = warp * 2;
    const int row1 = row0 + 1;

    const float* src0 = (row0 < BATCH) ? (xi + (size_t)row0 * DIM)
                                       : (xj + (size_t)(row0 - BATCH) * DIM);
    const float* src1 = (row1 < BATCH) ? (xi + (size_t)row1 * DIM)
                                       : (xj + (size_t)(row1 - BATCH) * DIM);

    float4 v0[4], v1[4];
    #pragma unroll
    for (int i = 0; i < 4; i++) v0[i] = ((const float4*)src0)[lane + 32 * i];
    #pragma unroll
    for (int i = 0; i < 4; i++) v1[i] = ((const float4*)src1)[lane + 32 * i];

    float ss0 = 0.0f, ss1 = 0.0f;
    #pragma unroll
    for (int i = 0; i < 4; i++) {
        ss0 += v0[i].x * v0[i].x + v0[i].y * v0[i].y + v0[i].z * v0[i].z + v0[i].w * v0[i].w;
        ss1 += v1[i].x * v1[i].x + v1[i].y * v1[i].y + v1[i].z * v1[i].z + v1[i].w * v1[i].w;
    }
    #pragma unroll
    for (int o = 16; o > 0; o >>= 1) {
        ss0 += __shfl_xor_sync(0xFFFFFFFFu, ss0, o);
        ss1 += __shfl_xor_sync(0xFFFFFFFFu, ss1, o);
    }

    const float inv0 = 1.0f / fmaxf(sqrtf(ss0), 1e-12f);
    const float inv1 = 1.0f / fmaxf(sqrtf(ss1), 1e-12f);

    #pragma unroll
    for (int i = 0; i < 4; i++) {
        __nv_bfloat162 h0 = __floats2bfloat162_rn(v0[i].x * inv0, v0[i].y * inv0);
        __nv_bfloat162 h1 = __floats2bfloat162_rn(v0[i].z * inv0, v0[i].w * inv0);
        uint2 u;
        u.x = *(uint32_t*)&h0;
        u.y = *(uint32_t*)&h1;
        ((uint2*)(g_zb + (size_t)row0 * DIM))[lane + 32 * i] = u;
    }
    #pragma unroll
    for (int i = 0; i < 4; i++) {
        __nv_bfloat162 h0 = __floats2bfloat162_rn(v1[i].x * inv1, v1[i].y * inv1);
        __nv_bfloat162 h1 = __floats2bfloat162_rn(v1[i].z * inv1, v1[i].w * inv1);
        uint2 u;
        u.x = *(uint32_t*)&h0;
        u.y = *(uint32_t*)&h1;
        ((uint2*)(g_zb + (size_t)row1 * DIM))[lane + 32 * i] = u;
    }

    if (lane == 0) {
        g_denom[row0] = 0.0f;
        g_denom[row1] = 0.0f;
        g_pos[row0] = 0.0f;
        g_pos[row1] = 0.0f;
    }
    if (blockIdx.x == 0 && threadIdx.x == 0) out[0] = 0.0f;
}

// ---------------------------------------------------------------------------
// Kernel 2: symmetric-aware fused sim tiles (upper-tri only) — EXACT R9/R12
// body, full grid 2080. Best measured configuration. DO NOT TOUCH.
// ---------------------------------------------------------------------------
__global__ __launch_bounds__(256, 2) void sim_kernel() {
    extern __shared__ char smem[];
    const uint32_t sbase = smem_u32(smem);
    const int tid = threadIdx.x;
    const int wid = tid >> 5;
    const int lane = tid & 31;

    // triangular decode: off(i) = i*64 - i*(i-1)/2
    const int t = blockIdx.x;
    int by = (int)(64.5f - sqrtf(64.5f * 64.5f - 2.0f * (float)t));
    while ((by + 1) * NTILES - ((by + 1) * by) / 2 <= t) by++;
    while (by * NTILES - (by * (by - 1)) / 2 > t) by--;
    const int bx = by + (t - (by * NTILES - (by * (by - 1)) / 2));

    const int rowBase = by * TILE;
    const int colBase = bx * TILE;
    const bool diag = (by == bx);

    const int warp_m = wid & 3;     // 0..3 -> 32-row strip
    const int warp_n = wid >> 2;    // 0..1 -> 64-col strip

    const __nv_bfloat16* __restrict__ zb = g_zb;

    // --- cp.async load mapping: 1024 16B units per tile, 4 per thread ---
    uint32_t ld_soff[4];
    const __nv_bfloat16* ld_ga[4];
    const __nv_bfloat16* ld_gb[4];
    #pragma unroll
    for (int it = 0; it < 4; it++) {
        int idx = tid + it * 256;
        int r = idx >> 3;
        int c16 = idx & 7;
        ld_soff[it] = (uint32_t)(r * 128 + ((c16 * 16) ^ ((r & 7) << 4)));
        ld_ga[it] = zb + (size_t)(rowBase + r) * DIM + c16 * 8;
        ld_gb[it] = zb + (size_t)(colBase + r) * DIM + c16 * 8;
    }

    // --- ldmatrix address components (swizzle folded into col xor) ---
    uint32_t aRow[2], aMask[2];
    #pragma unroll
    for (int mt = 0; mt < 2; mt++) {
        int r = warp_m * 32 + mt * 16 + (lane & 15);
        aRow[mt] = (uint32_t)(r * 128);
        aMask[mt] = (uint32_t)((r & 7) << 4);
    }
    const uint32_t aColK = (uint32_t)((lane >> 4) * 16);

    uint32_t bRow[4], bMask[4];
    const int q = lane >> 3;
    #pragma unroll
    for (int p = 0; p < 4; p++) {
        int r = warp_n * 64 + (2 * p + (q >> 1)) * 8 + (lane & 7);
        bRow[p] = (uint32_t)(r * 128);
        bMask[p] = (uint32_t)((r & 7) << 4);
    }
    const uint32_t bColK = (uint32_t)((q & 1) * 16);

    float acc[2][8][4];
    #pragma unroll
    for (int mt = 0; mt < 2; mt++)
        #pragma unroll
        for (int nt = 0; nt < 8; nt++)
            #pragma unroll
            for (int k = 0; k < 4; k++) acc[mt][nt][k] = 0.0f;

    // --- prologue: chunk 0 -> buffer 0 ---
    #pragma unroll
    for (int it = 0; it < 4; it++) {
        cp_async16(sbase + SM_A(0) + ld_soff[it], ld_ga[it]);
        cp_async16(sbase + SM_B(0) + ld_soff[it], ld_gb[it]);
    }
    cp_commit();

    for (int kk = 0; kk < NCHUNKS; kk++) {
        const int buf = kk & 1;
        if (kk + 1 < NCHUNKS) {
            const int nb = (kk + 1) & 1;
            const int koff = (kk + 1) * KCHUNK;
            #pragma unroll
            for (int it = 0; it < 4; it++) {
                cp_async16(sbase + SM_A(nb) + ld_soff[it], ld_ga[it] + koff);
                cp_async16(sbase + SM_B(nb) + ld_soff[it], ld_gb[it] + koff);
            }
            cp_commit();
            cp_wait<1>();
        } else {
            cp_wait<0>();
        }
        __syncthreads();

        const uint32_t abase = sbase + SM_A(buf);
        const uint32_t bbase = sbase + SM_B(buf);

        #pragma unroll
        for (int kt = 0; kt < 4; kt++) {
            const uint32_t kb = (uint32_t)(kt * 32);
            uint32_t a[2][4];
            #pragma unroll
            for (int mt = 0; mt < 2; mt++)
                ldsm_x4(a[mt], abase + aRow[mt] + ((kb + aColK) ^ aMask[mt]));

            uint32_t b[8][2];
            #pragma unroll
            for (int p = 0; p < 4; p++) {
                uint32_t r4[4];
                ldsm_x4(r4, bbase + bRow[p] + ((kb + bColK) ^ bMask[p]));
                b[2 * p][0] = r4[0]; b[2 * p][1] = r4[1];
                b[2 * p + 1][0] = r4[2]; b[2 * p + 1][1] = r4[3];
            }

            #pragma unroll
            for (int mt = 0; mt < 2; mt++)
                #pragma unroll
                for (int nt = 0; nt < 8; nt++)
                    mma16816(acc[mt][nt], a[mt], b[nt]);
        }
        __syncthreads();   // protect buffers before next iteration's cp.async
    }

    // --- fused epilogue ---
    const int g = lane >> 2;
    const int cb0 = colBase + warp_n * 64 + (lane & 3) * 2;

    if (diag) {
        #pragma unroll
        for (int mt = 0; mt < 2; mt++) {
            const int r_lo = rowBase + warp_m * 32 + mt * 16 + g;
            const int r_hi = r_lo + 8;
            float sum_lo = 0.0f, sum_hi = 0.0f;
            #pragma unroll
            for (int nt = 0; nt < 8; nt++) {
                const int c0 = cb0 + nt * 8;
                if (c0 != r_lo)     sum_lo += fast_exp2s(acc[mt][nt][0]);
                if (c0 + 1 != r_lo) sum_lo += fast_exp2s(acc[mt][nt][1]);
                if (c0 != r_hi)     sum_hi += fast_exp2s(acc[mt][nt][2]);
                if (c0 + 1 != r_hi) sum_hi += fast_exp2s(acc[mt][nt][3]);
            }
            #pragma unroll
            for (int o = 1; o < 4; o <<= 1) {
                sum_lo += __shfl_xor_sync(0xFFFFFFFFu, sum_lo, o);
                sum_hi += __shfl_xor_sync(0xFFFFFFFFu, sum_hi, o);
            }
            if ((lane & 3) == 0) {
                atomicAdd(&g_denom[r_lo], sum_lo);
                atomicAdd(&g_denom[r_hi], sum_hi);
            }
        }
    } else {
        // off-diagonal: every exp feeds a row sum AND a column sum (symmetry).
        float csum[8][2];
        #pragma unroll
        for (int nt = 0; nt < 8; nt++) { csum[nt][0] = 0.0f; csum[nt][1] = 0.0f; }

        #pragma unroll
        for (int mt = 0; mt < 2; mt++) {
            const int r_lo = rowBase + warp_m * 32 + mt * 16 + g;
            const int r_hi = r_lo + 8;
            const int p_lo = r_lo + BATCH;   // rows < cols here
            const int p_hi = r_hi + BATCH;

            float sum_lo = 0.0f, sum_hi = 0.0f;
            #pragma unroll
            for (int nt = 0; nt < 8; nt++) {
                const int c0 = cb0 + nt * 8;
                const float s00 = acc[mt][nt][0];
                const float s01 = acc[mt][nt][1];
                const float s10 = acc[mt][nt][2];
                const float s11 = acc[mt][nt][3];
                const float e00 = fast_exp2s(s00);
                const float e01 = fast_exp2s(s01);
                const float e10 = fast_exp2s(s10);
                const float e11 = fast_exp2s(s11);
                sum_lo += e00 + e01;
                sum_hi += e10 + e11;
                csum[nt][0] += e00 + e10;
                csum[nt][1] += e01 + e11;
                if (c0 == p_lo)     { g_pos[r_lo] = s00; g_pos[c0] = s00; }
                if (c0 + 1 == p_lo) { g_pos[r_lo] = s01; g_pos[c0 + 1] = s01; }
                if (c0 == p_hi)     { g_pos[r_hi] = s10; g_pos[c0] = s10; }
                if (c0 + 1 == p_hi) { g_pos[r_hi] = s11; g_pos[c0 + 1] = s11; }
            }
            #pragma unroll
            for (int o = 1; o < 4; o <<= 1) {
                sum_lo += __shfl_xor_sync(0xFFFFFFFFu, sum_lo, o);
                sum_hi += __shfl_xor_sync(0xFFFFFFFFu, sum_hi, o);
            }
            if ((lane & 3) == 0) {
                atomicAdd(&g_denom[r_lo], sum_lo);
                atomicAdd(&g_denom[r_hi], sum_hi);
            }
        }

        #pragma unroll
        for (int nt = 0; nt < 8; nt++) {
            float c0s = csum[nt][0];
            float c1s = csum[nt][1];
            #pragma unroll
            for (int o = 4; o < 32; o <<= 1) {
                c0s += __shfl_xor_sync(0xFFFFFFFFu, c0s, o);
                c1s += __shfl_xor_sync(0xFFFFFFFFu, c1s, o);
            }
            if (g == 0) {
                const int c0 = cb0 + nt * 8;
                atomicAdd(&g_denom[c0], c0s);
                atomicAdd(&g_denom[c0 + 1], c1s);
            }
        }
    }
}

// ---------------------------------------------------------------------------
// Kernel 3: distributed final reduction — 32 blocks x 256 threads, __logf
// (MUFU.LG2), shfl-based block reduce, one atomicAdd per block into out
// (zeroed by norm_kernel).
// ---------------------------------------------------------------------------
__global__ __launch_bounds__(256) void reduce_kernel(float* __restrict__ out) {
    const int i = blockIdx.x * 256 + threadIdx.x;
    float v = __logf(g_denom[i]) - 2.0f * g_pos[i];
    #pragma unroll
    for (int o = 16; o > 0; o >>= 1) v += __shfl_xor_sync(0xFFFFFFFFu, v, o);

    __shared__ float ws[8];
    if ((threadIdx.x & 31) == 0) ws[threadIdx.x >> 5] = v;
    __syncthreads();
    if (threadIdx.x < 32) {
        float s = (threadIdx.x < 8) ? ws[threadIdx.x] : 0.0f;
        #pragma unroll
        for (int o = 4; o > 0; o >>= 1) s += __shfl_xor_sync(0xFFFFFFFFu, s, o);
        if (threadIdx.x == 0) atomicAdd(out, s * (1.0f / (float)NTOT));
    }
}

// ---------------------------------------------------------------------------
extern "C" void kernel_launch(void* const* d_in, const int* in_sizes, int n_in,
                              void* d_out, int out_size) {
    const float* x_i = (const float*)d_in[0];
    const float* x_j = (const float*)d_in[1];
    float* out = (float*)d_out;

    cudaFuncSetAttribute(sim_kernel, cudaFuncAttributeMaxDynamicSharedMemorySize, SM_TOTAL);

    norm_kernel<<<NTOT / 16, 256>>>(x_i, x_j, out);   // 512 blocks, 2 rows/warp
    sim_kernel<<<NCTAS, 256, SM_TOTAL>>>();           // full 2080-tile grid
    reduce_kernel<<<NTOT / 256, 256>>>(out);          // 32 blocks
}